// round 9
// baseline (speedup 1.0000x reference)
#include <cuda_runtime.h>
#include <cuda_bf16.h>
#include <cstddef>

// Problem constants (fixed by reference: L=16, KV=4, V=2, B=512)
#define S_  65536
#define R_  4096
#define D_  16
#define B_  512
#define PS_ (B_ * R_)           // 2097152
#define NC_ ((size_t)B_ * S_)   // 33554432

#define NTILES   (B_ * 4)       // 2048 quarter-row tiles
#define NBLOCKS  740            // 148 SMs x 5 blocks/SM = exactly one wave

// Persistent grid-stride version of the R7 champion. One tile = 256 threads x
// one quarter-row (1024 r, 16384 s). Warps fully decoupled within a tile
// (phase 2 of warp w reads only bvf[w*128..+128) which it wrote itself), so
// only __syncwarp is needed; across tiles the same warp reuses its own bvf
// slice (program order + syncwarp make that safe). Grid = one full wave so
// there are no wave-transition gaps — every SM streams continuously.
// Phase 1: min/argmin over d via 16 coalesced strided float4 __ldcs (cost is
//          read exactly once globally). prev_state is pure ALU since
//          state_candidates[r,d] = r + (d<<12) by construction.
// Phase 2: sector-minimal coalesced epilogue: 2 lut float4 loads (L2-resident)
//          + 2 nc float2 __stcs per lane/iter; best_val broadcast from smem.
__global__ __launch_bounds__(256)
void trellis_fused_kernel(const float*  __restrict__ lut,   // [S,2]
                          const float*  __restrict__ cost,  // [B,S]
                          const float*  __restrict__ orig,  // [B,2]
                          float*        __restrict__ ps_out,
                          float*        __restrict__ nc_out)
{
    __shared__ float bvf[1024];     // warp w owns [w*128, w*128+128)

    const int tid  = threadIdx.x;
    const int lane = tid & 31;
    const int w    = tid >> 5;
    const float4* __restrict__ lvf4 = (const float4*)lut;

    for (int tile = blockIdx.x; tile < NTILES; tile += NBLOCKS) {
        const int b  = tile >> 2;          // batch row
        const int q  = tile & 3;           // quarter of the row
        const int rq = (q << 8) + tid;     // rq in [0,1024)

        const float4* __restrict__ cbv = (const float4*)(cost + (size_t)b * S_);

        // ---- Phase 1: min/argmin over d (strict '<' => first occurrence)
        float4 best = __ldcs(&cbv[rq]);
        int bdx = 0, bdy = 0, bdz = 0, bdw = 0;
        #pragma unroll
        for (int d = 1; d < D_; ++d) {
            float4 v = __ldcs(&cbv[d * (R_ / 4) + rq]);
            if (v.x < best.x) { best.x = v.x; bdx = d; }
            if (v.y < best.y) { best.y = v.y; bdy = d; }
            if (v.z < best.z) { best.z = v.z; bdz = d; }
            if (v.w < best.w) { best.w = v.w; bdw = d; }
        }

        ((float4*)bvf)[tid] = best;

        // prev_state[b,r] = sc[r,best_idx] = r + (best_idx << 12)  (pure ALU)
        if (ps_out) {
            const int r0 = rq << 2;
            float4 ps;
            ps.x = (float)(r0 + 0 + (bdx << 12));
            ps.y = (float)(r0 + 1 + (bdy << 12));
            ps.z = (float)(r0 + 2 + (bdz << 12));
            ps.w = (float)(r0 + 3 + (bdw << 12));
            __stcs(&((float4*)ps_out)[(size_t)b * (R_ / 4) + rq], ps);
        }

        __syncwarp();   // phase 2 reads only this warp's own bvf slice

        // ---- Phase 2: coalesced new_cost epilogue (warp-independent)
        if (nc_out) {
            const float o0 = __ldg(&orig[2 * b + 0]);
            const float o1 = __ldg(&orig[2 * b + 1]);

            float2* __restrict__ nc2 = (float2*)(nc_out + (size_t)b * S_);
            const int hb = q * 8192 + w * 1024;    // warp's lut-f4 / nc-f2 base

            #pragma unroll
            for (int it = 0; it < 16; ++it) {
                const int jb = hb + it * 64;              // 64 lut f4s = 128 states
                const float4 A  = __ldg(&lvf4[jb + lane]);
                const float4 Bv = __ldg(&lvf4[jb + 32 + lane]);

                const int rbase = w * 128 + it * 8 + (lane >> 3);
                const float bvA = bvf[rbase];
                const float bvB = bvf[rbase + 4];

                float dx, dy;
                float2 oA, oB;
                dx = A.x  - o0; dy = A.y  - o1; oA.x = fmaf(dx, dx, dy * dy) + bvA;
                dx = A.z  - o0; dy = A.w  - o1; oA.y = fmaf(dx, dx, dy * dy) + bvA;
                dx = Bv.x - o0; dy = Bv.y - o1; oB.x = fmaf(dx, dx, dy * dy) + bvB;
                dx = Bv.z - o0; dy = Bv.w - o1; oB.y = fmaf(dx, dx, dy * dy) + bvB;

                __stcs(&nc2[jb + lane],      oA);
                __stcs(&nc2[jb + 32 + lane], oB);
            }
        }

        __syncwarp();   // don't overwrite bvf while any lane still reads it
    }
}

extern "C" void kernel_launch(void* const* d_in, const int* in_sizes, int n_in,
                              void* d_out, int out_size)
{
    const float* lut  = (const float*)d_in[0];
    const float* cost = (const float*)d_in[1];
    const float* orig = (const float*)d_in[2];
    float* out = (float*)d_out;

    float* ps_out = nullptr;
    float* nc_out = nullptr;
    const size_t osz = (size_t)out_size;
    if (osz >= (size_t)PS_ + NC_) {
        ps_out = out;
        nc_out = out + PS_;
    } else if (osz == NC_) {
        nc_out = out;
    } else {
        ps_out = out;
    }

    trellis_fused_kernel<<<NBLOCKS, 256>>>(lut, cost, orig, ps_out, nc_out);
}